// round 4
// baseline (speedup 1.0000x reference)
#include <cuda_runtime.h>
#include <math.h>

#define NB   128
#define NT   256
#define BR   32
#define ST0  200      // layer-0 input row stride (192 cols used)
#define STA  264      // activation row stride

// smem layout (floats)
#define OFF_SIN   0
#define OFF_A1    (OFF_SIN + BR*ST0)          // 6400
#define OFF_A2    (OFF_A1 + BR*STA)           // 14848
#define OFF_SW0   (OFF_A2 + BR*STA)           // 23296
#define OFF_SW1   (OFF_SW0 + 32*256)          // 31488
#define OFF_SWF   (OFF_SW1 + 32*256)          // 39680
#define OFF_XS    (OFF_SWF + 256*32)          // 47872  (32 x 33)
#define OFF_TE    (OFF_XS + 32*33)            // 48928
#define OFF_HT    (OFF_TE + 16)
#define OFF_TF    (OFF_HT + 32)
#define OFF_CF    (OFF_TF + 16)
#define SMEM_FLOATS (OFF_CF + 16)
#define SMEM_BYTES  (SMEM_FLOATS * 4)

// ---------------- threefry2x32-20 (exact JAX) ------------------------------
__device__ __forceinline__ unsigned rotl32(unsigned x, int r) {
    return __funnelshift_l(x, x, r);
}
__device__ __forceinline__ void threefry2x32(unsigned k0, unsigned k1,
                                             unsigned &x0, unsigned &x1) {
    unsigned k2 = k0 ^ k1 ^ 0x1BD11BDAu;
#define TFR(r) { x0 += x1; x1 = rotl32(x1, r); x1 ^= x0; }
    x0 += k0; x1 += k1;
    TFR(13) TFR(15) TFR(26) TFR(6)
    x0 += k1; x1 += k2 + 1u;
    TFR(17) TFR(29) TFR(16) TFR(24)
    x0 += k2; x1 += k0 + 2u;
    TFR(13) TFR(15) TFR(26) TFR(6)
    x0 += k0; x1 += k1 + 3u;
    TFR(17) TFR(29) TFR(16) TFR(24)
    x0 += k1; x1 += k2 + 4u;
    TFR(13) TFR(15) TFR(26) TFR(6)
    x0 += k2; x1 += k0 + 5u;
#undef TFR
}

// ---------------- XLA ErfInv f32 (Giles) ------------------------------------
__device__ __forceinline__ float erfinv_xla(float x) {
    float w = -log1pf(-x * x);
    float p;
    if (w < 5.0f) {
        w -= 2.5f;
        p = 2.81022636e-08f;
        p = fmaf(p, w, 3.43273939e-07f);
        p = fmaf(p, w, -3.5233877e-06f);
        p = fmaf(p, w, -4.39150654e-06f);
        p = fmaf(p, w, 0.00021858087f);
        p = fmaf(p, w, -0.00125372503f);
        p = fmaf(p, w, -0.00417768164f);
        p = fmaf(p, w, 0.246640727f);
        p = fmaf(p, w, 1.50140941f);
    } else {
        w = sqrtf(w) - 3.0f;
        p = -0.000200214257f;
        p = fmaf(p, w, 0.000100950558f);
        p = fmaf(p, w, 0.00134934322f);
        p = fmaf(p, w, -0.00367342844f);
        p = fmaf(p, w, 0.00573950773f);
        p = fmaf(p, w, -0.0076224613f);
        p = fmaf(p, w, 0.00943887047f);
        p = fmaf(p, w, 1.00167406f);
        p = fmaf(p, w, 2.83297682f);
    }
    return p * x;
}

__device__ __forceinline__ float mish_f(float x) {
    if (x > 20.0f) return x;
    float u = expf(x);
    float s = u * (u + 2.0f);
    return x * (s / (s + 2.0f));
}

// ---------------- cp.async helpers ------------------------------------------
__device__ __forceinline__ void cp16(float* dst, const float* src) {
    unsigned sa = (unsigned)__cvta_generic_to_shared(dst);
    asm volatile("cp.async.cg.shared.global [%0], [%1], 16;\n" :: "r"(sa), "l"(src));
}
#define CP_COMMIT() asm volatile("cp.async.commit_group;\n" ::: "memory")
#define CP_WAIT(n)  asm volatile("cp.async.wait_group %0;\n" :: "n"(n) : "memory")

// stage one 32x256 weight chunk (rows >= `rows` are zero-filled)
__device__ __forceinline__ void stage_chunk(float* SWb, const float* Wsrc,
                                            int rows, int tid) {
#pragma unroll
    for (int l = 0; l < 8; ++l) {
        int idx = l * 256 + tid;       // 16B-chunk id; float offset = 4*idx
        int row = idx >> 6;
        if (row < rows) cp16(SWb + 4 * idx, Wsrc + 4 * idx);
        else *reinterpret_cast<float4*>(SWb + 4 * idx) = make_float4(0.f, 0.f, 0.f, 0.f);
    }
}

// ------------- dense (K -> 256), 32 rows, cp.async double-buffered ----------
template <int KP, int KREAL, int INST, int OUTST, bool DOMISH>
__device__ __forceinline__ void dense_layer(const float* __restrict__ W,
                                            const float* __restrict__ bias,
                                            const float* __restrict__ IN,
                                            float* __restrict__ OUT,
                                            float* __restrict__ SW0,
                                            float* __restrict__ SW1, int tid) {
    constexpr int NCH = KP / 32;
    const int ty = tid >> 6;          // 4 row-groups of 8 rows
    const int tx = tid & 63;          // 64 col-groups of 4 cols
    float acc[8][4];
#pragma unroll
    for (int r = 0; r < 8; ++r)
#pragma unroll
        for (int c = 0; c < 4; ++c) acc[r][c] = 0.f;

    stage_chunk(SW0, W, (KREAL < 32 ? KREAL : 32), tid);
    CP_COMMIT();

    const float* inbase = IN + (ty * 8) * INST;

#pragma unroll 1
    for (int c = 0; c < NCH; ++c) {
        if (c + 1 < NCH) {
            int rows = KREAL - (c + 1) * 32;
            if (rows > 32) rows = 32;
            stage_chunk((c & 1) ? SW0 : SW1, W + (c + 1) * 32 * 256, rows, tid);
            CP_COMMIT();
            CP_WAIT(1);
        } else {
            CP_WAIT(0);
        }
        __syncthreads();
        const float* SW = (c & 1) ? SW1 : SW0;
        const float* inrow = inbase + c * 32;
#pragma unroll 2
        for (int k4 = 0; k4 < 32; k4 += 4) {
            float4 av[8];
#pragma unroll
            for (int r = 0; r < 8; ++r)
                av[r] = *reinterpret_cast<const float4*>(inrow + r * INST + k4);
#pragma unroll
            for (int kk = 0; kk < 4; ++kk) {
                float4 bv = *reinterpret_cast<const float4*>(SW + ((k4 + kk) << 8) + (tx << 2));
#pragma unroll
                for (int r = 0; r < 8; ++r) {
                    float a = reinterpret_cast<const float*>(&av[r])[kk];
                    acc[r][0] = fmaf(a, bv.x, acc[r][0]);
                    acc[r][1] = fmaf(a, bv.y, acc[r][1]);
                    acc[r][2] = fmaf(a, bv.z, acc[r][2]);
                    acc[r][3] = fmaf(a, bv.w, acc[r][3]);
                }
            }
        }
        __syncthreads();
    }

    float4 bb = *reinterpret_cast<const float4*>(bias + (tx << 2));
#pragma unroll
    for (int r = 0; r < 8; ++r) {
        float v0 = acc[r][0] + bb.x, v1 = acc[r][1] + bb.y;
        float v2 = acc[r][2] + bb.z, v3 = acc[r][3] + bb.w;
        if (DOMISH) { v0 = mish_f(v0); v1 = mish_f(v1); v2 = mish_f(v2); v3 = mish_f(v3); }
        *reinterpret_cast<float4*>(OUT + (ty * 8 + r) * OUTST + (tx << 2)) =
            make_float4(v0, v1, v2, v3);
    }
}

// ---------------- persistent sampler: all 1000 steps in one kernel ----------
__global__ void __launch_bounds__(NT, 1)
diff_all(const float* __restrict__ state, const float* __restrict__ x_init,
         const float* __restrict__ w_t1, const float* __restrict__ b_t1,
         const float* __restrict__ w_t2, const float* __restrict__ b_t2,
         const float* __restrict__ w0,  const float* __restrict__ b0,
         const float* __restrict__ w1,  const float* __restrict__ b1,
         const float* __restrict__ w2,  const float* __restrict__ b2,
         const float* __restrict__ wf,  const float* __restrict__ bf,
         float* __restrict__ outp)
{
    extern __shared__ float sm[];
    float*    S_IN = sm + OFF_SIN;
    float*    A1   = sm + OFF_A1;
    float*    A2   = sm + OFF_A2;
    float*    SW0  = sm + OFF_SW0;
    float*    SW1  = sm + OFF_SW1;
    float*    SWF  = sm + OFF_SWF;
    float*    XS   = sm + OFF_XS;
    float*    TE   = sm + OFF_TE;
    float*    HT   = sm + OFF_HT;
    float*    TF   = sm + OFF_TF;
    float*    CF   = sm + OFF_CF;
    unsigned* CFu  = reinterpret_cast<unsigned*>(CF);

    const int tid = threadIdx.x;
    const int r0  = blockIdx.x * BR;

    // ---- one-time staging: x, state, wf, zero-pad, freqs
    for (int idx = tid; idx < BR * 32; idx += NT) {
        int r = idx >> 5, c = idx & 31;
        XS[r * 33 + c] = x_init[(r0 + r) * 32 + c];
    }
    for (int idx = tid; idx < BR * 128; idx += NT) {
        int r = idx >> 7, c = idx & 127;
        S_IN[r * ST0 + 48 + c] = state[(r0 + r) * 128 + c];
    }
    for (int idx = tid; idx < BR * 16; idx += NT) {
        int r = idx >> 4, c = idx & 15;
        S_IN[r * ST0 + 176 + c] = 0.f;
    }
    for (int idx = tid; idx < 256 * 32; idx += NT) SWF[idx] = wf[idx];
    __syncthreads();

#pragma unroll 1
    for (int i = 999; i >= 0; --i) {
        // ---- per-step scalars (one thread)
        if (tid == 0) {
            double nn    = (double)(i + 1);
            double ac    = exp(-1e-4 * nn - 4.95e-6 * nn * nn);
            double nm    = nn - 1.0;
            double acp   = (i == 0) ? 1.0 : exp(-1e-4 * nm - 4.95e-6 * nm * nm);
            double beta  = 1.0 - exp(-1e-4 - 4.95e-6 * (2.0 * nn - 1.0));
            double alpha = 1.0 - beta;
            CF[0] = (float)sqrt(1.0 / ac);                       // sr
            CF[1] = (float)sqrt(1.0 / ac - 1.0);                 // srm1
            CF[2] = (float)(beta * sqrt(acp) / (1.0 - ac));      // c1
            CF[3] = (float)((1.0 - acp) * sqrt(alpha) / (1.0 - ac)); // c2
            double pv = beta * (1.0 - acp) / (1.0 - ac);
            if (pv < 1e-20) pv = 1e-20;
            float lv = (float)log(pv);
            CF[4] = (float)exp((double)(0.5f * lv));             // sigma
            unsigned a0 = 0u, a1 = (unsigned)i;
            threefry2x32(0u, 1u, a0, a1);
            CFu[5] = a0; CFu[6] = a1;                            // folded key
        }
        // ---- time embedding + tiny MLP (batch-invariant)
        if (tid < 8) {
            float c8   = (float)(-9.210340371976184 / 7.0);
            float freq = expf(c8 * (float)tid);
            float ang  = (float)i * freq;
            TE[tid]     = (float)sin((double)ang);
            TE[tid + 8] = (float)cos((double)ang);
        }
        __syncthreads();
        if (tid < 32) {
            float h = b_t1[tid];
#pragma unroll
            for (int k = 0; k < 16; ++k) h = fmaf(TE[k], w_t1[k * 32 + tid], h);
            HT[tid] = mish_f(h);
        }
        __syncthreads();
        if (tid < 16) {
            float v = b_t2[tid];
#pragma unroll
            for (int k = 0; k < 32; ++k) v = fmaf(HT[k], w_t2[k * 16 + tid], v);
            TF[tid] = v;
        }
        __syncthreads();
        // ---- fill layer-0 input: x cols [0,32), tf cols [32,48)
        for (int idx = tid; idx < BR * 32; idx += NT) {
            int r = idx >> 5, c = idx & 31;
            S_IN[r * ST0 + c] = XS[r * 33 + c];
        }
        for (int idx = tid; idx < BR * 16; idx += NT) {
            int r = idx >> 4, c = idx & 15;
            S_IN[r * ST0 + 32 + c] = TF[c];
        }
        // dense_layer's first internal __syncthreads covers the fills above

        dense_layer<192, 176, ST0, STA, true>(w0, b0, S_IN, A1, SW0, SW1, tid);
        dense_layer<256, 256, STA, STA, true>(w1, b1, A1,  A2, SW0, SW1, tid);
        dense_layer<256, 256, STA, STA, true>(w2, b2, A2,  A1, SW0, SW1, tid);
        __syncthreads();

        // ---- final 256 -> 32 : row = tid>>3, cols (tid&7)*4 .. +3
        const int row = tid >> 3;
        const int cg  = tid & 7;
        float4 acc = make_float4(0.f, 0.f, 0.f, 0.f);
        const float* inr = A1 + row * STA;
#pragma unroll 4
        for (int k4 = 0; k4 < 256; k4 += 4) {
            float4 a4 = *reinterpret_cast<const float4*>(inr + k4);
#pragma unroll
            for (int kk = 0; kk < 4; ++kk) {
                float a = reinterpret_cast<const float*>(&a4)[kk];
                float4 wv = *reinterpret_cast<const float4*>(SWF + ((k4 + kk) << 5) + (cg << 2));
                acc.x = fmaf(a, wv.x, acc.x);
                acc.y = fmaf(a, wv.y, acc.y);
                acc.z = fmaf(a, wv.z, acc.z);
                acc.w = fmaf(a, wv.w, acc.w);
            }
        }
        float4 bb = *reinterpret_cast<const float4*>(bf + (cg << 2));
        float eps[4] = { acc.x + bb.x, acc.y + bb.y, acc.z + bb.z, acc.w + bb.w };

        float sr = CF[0], srm1 = CF[1], c1 = CF[2], c2 = CF[3], sig = CF[4];
        unsigned fk0 = CFu[5], fk1 = CFu[6];

        const int R = r0 + row;
#pragma unroll
        for (int cc = 0; cc < 4; ++cc) {
            int   j  = (cg << 2) + cc;
            float xv = XS[row * 33 + j];
            float x0 = fminf(1.f, fmaxf(-1.f, sr * xv - srm1 * eps[cc]));
            float mean = c1 * x0 + c2 * xv;
            if (i != 0) {
                unsigned f = (unsigned)(R * 32 + j);
                unsigned b0r = 0u, b1r = f;
                threefry2x32(fk0, fk1, b0r, b1r);
                unsigned bits = b0r ^ b1r;
                float fv = __uint_as_float((bits >> 9) | 0x3f800000u) - 1.0f;
                const float lo = -0.99999994f;               // nextafter(-1,0)
                float u   = fmaxf(lo, fmaf(fv, 2.0f, lo));   // (1-lo) == 2.0f in f32
                float nrm = 1.4142135623730951f * erfinv_xla(u);
                XS[row * 33 + j] = mean + sig * nrm;
            } else {
                float xf = fminf(1.f, fmaxf(-1.f, mean));
                XS[row * 33 + j] = xf;
                outp[R * 32 + j] = xf;
            }
        }
        __syncthreads();   // XS fully updated before next step reads it
    }
}

extern "C" void kernel_launch(void* const* d_in, const int* in_sizes, int n_in,
                              void* d_out, int out_size) {
    const float* state = (const float*)d_in[0];
    const float* xinit = (const float*)d_in[1];
    const float* w_t1  = (const float*)d_in[2];
    const float* b_t1  = (const float*)d_in[3];
    const float* w_t2  = (const float*)d_in[4];
    const float* b_t2  = (const float*)d_in[5];
    const float* w0    = (const float*)d_in[6];
    const float* b0    = (const float*)d_in[7];
    const float* w1    = (const float*)d_in[8];
    const float* b1    = (const float*)d_in[9];
    const float* w2    = (const float*)d_in[10];
    const float* b2    = (const float*)d_in[11];
    const float* wf    = (const float*)d_in[12];
    const float* bf    = (const float*)d_in[13];
    float* outp = (float*)d_out;

    cudaFuncSetAttribute(diff_all, cudaFuncAttributeMaxDynamicSharedMemorySize, SMEM_BYTES);

    diff_all<<<NB, NT, SMEM_BYTES>>>(state, xinit,
        w_t1, b_t1, w_t2, b_t2,
        w0, b0, w1, b1, w2, b2, wf, bf, outp);
}